// round 4
// baseline (speedup 1.0000x reference)
#include <cuda_runtime.h>
#include <cub/cub.cuh>

// ---------------------------------------------------------------------------
// Graph U-Net forward — CSR aggregation, fused BN-in-consumer, fused scan,
// 2-stream overlap. Launch-count-optimized.
// ---------------------------------------------------------------------------
#define cN0 80000
#define cN1 40000
#define cN2 20000
#define cN3 10000
#define cNE 1280000
#define HID 64
#define BN_EPS 1e-5f
#define TPB 256
#define GRIDE 1184
#define FULLM 0xffffffffu

// ------------------------- static device scratch ---------------------------
__device__ __align__(16) float g_X0[cN0 * HID];
__device__ __align__(16) float g_X1[cN1 * HID];
__device__ __align__(16) float g_X2[cN2 * HID];
__device__ __align__(16) float g_H [cN0 * HID];
__device__ __align__(16) float g_Y [cN0 * HID];   // down-path agg output (transient)
__device__ __align__(16) float g_YD3[cN3 * HID];  // block3 agg output (persists)
__device__ __align__(16) float g_YU0[cN2 * HID];  // up0 agg output (persists)
__device__ __align__(16) float g_YU1[cN1 * HID];  // up1 agg output (persists)
__device__ int   g_deg[cN0 + 1];
__device__ int   g_cursor[cN0];
__device__ int   g_rs0[cN0 + 1], g_rs1[cN1 + 1], g_rs2[cN2 + 1], g_rs3[cN3 + 1];
__device__ float g_dinv0_2[cN0], g_dinv0_1[cN0];
__device__ float g_dinv1[cN1], g_dinv2[cN2], g_dinv3[cN3];
__device__ int   g_csr0[cNE], g_csr1[cNE], g_csr2[cNE], g_csr3[cNE];
__device__ int   g_src1[cNE], g_dst1[cNE];
__device__ int   g_src2[cNE], g_dst2[cNE];
__device__ int   g_src3[cNE], g_dst3[cNE];
__device__ int   g_cnt[4];
__device__ float g_keys[cN0], g_keysOut[cN0];
__device__ int   g_idx[cN0];
__device__ int   g_perm0[cN0], g_perm1[cN1], g_perm2[cN2];
__device__ int   g_map0[cN0], g_map1[cN1], g_map2[cN2];
__device__ float g_statsAll[6 * 128];             // per-block BN stat slots
__device__ float g_h1[cN0];
__device__ __align__(256) unsigned char g_cubtmp[8 * 1024 * 1024];

// ------------------------------- kernels -----------------------------------
__global__ void k_zeroi(int* __restrict__ p, int n) {
    int t = blockIdx.x * blockDim.x + threadIdx.x;
    if (t < n) p[t] = 0;
}

__global__ void k_hist0(const int* __restrict__ dst, int* __restrict__ deg) {
    for (int t = blockIdx.x * blockDim.x + threadIdx.x; t < cNE; t += gridDim.x * blockDim.x)
        atomicAdd(&deg[dst[t]], 1);
}

// single-block fused exclusive scan + cursor + dinv (n <= 80000)
__global__ void __launch_bounds__(1024)
k_scanprep(const int* __restrict__ deg, int* __restrict__ rs, int* __restrict__ cursor,
           float* __restrict__ dinvA, float fillA,
           float* __restrict__ dinvB, float fillB, int n) {
    __shared__ int warpsum[32];
    int tid = threadIdx.x;
    int lane = tid & 31, wid = tid >> 5;
    int chunk = (n + 1023) >> 10;
    int lo = min(tid * chunk, n), hi = min(lo + chunk, n);
    int s = 0;
    for (int i = lo; i < hi; i++) s += deg[i];
    int v = s;
    #pragma unroll
    for (int o = 1; o < 32; o <<= 1) {
        int t = __shfl_up_sync(FULLM, v, o);
        if (lane >= o) v += t;
    }
    if (lane == 31) warpsum[wid] = v;
    __syncthreads();
    if (wid == 0) {
        int w = warpsum[lane];
        #pragma unroll
        for (int o = 1; o < 32; o <<= 1) {
            int t = __shfl_up_sync(FULLM, w, o);
            if (lane >= o) w += t;
        }
        warpsum[lane] = w;
    }
    __syncthreads();
    int base = v - s + (wid ? warpsum[wid - 1] : 0);
    int run = base;
    for (int i = lo; i < hi; i++) {
        int d = deg[i];
        rs[i] = run;
        cursor[i] = run;
        float df = (float)d;
        dinvA[i] = rsqrtf(df + fillA);
        if (dinvB) dinvB[i] = rsqrtf(df + fillB);
        run += d;
    }
    if (tid == 1023) rs[n] = run;
}

__global__ void k_scatter(const int* __restrict__ srcC, const int* __restrict__ dstC,
                          int* __restrict__ cursor, int* __restrict__ csr,
                          const int* __restrict__ cntp, int nfix) {
    int cnt = cntp ? *cntp : nfix;
    for (int t = blockIdx.x * blockDim.x + threadIdx.x; t < cnt; t += gridDim.x * blockDim.x) {
        int pos = atomicAdd(&cursor[dstC[t]], 1);
        csr[pos] = srcC[t];
    }
}

__global__ void k_mapset(int* __restrict__ map, const int* __restrict__ perm,
                         int k, int* __restrict__ cntZ) {
    int t = blockIdx.x * blockDim.x + threadIdx.x;
    if (t == 0) *cntZ = 0;
    if (t < k) map[perm[t]] = t;
}

// compact remap + dst-degree histogram; warp-aggregated counter pushes
__global__ void k_remap_hist(const int* __restrict__ srcP, const int* __restrict__ dstP,
                             const int* __restrict__ map, int* __restrict__ srcN,
                             int* __restrict__ dstN, int* __restrict__ cntN,
                             int* __restrict__ deg, const int* __restrict__ cntp, int nfix) {
    int cnt = cntp ? *cntp : nfix;
    int lane = threadIdx.x & 31;
    int stride = gridDim.x * blockDim.x;
    for (int t = blockIdx.x * blockDim.x + threadIdx.x;; t += stride) {
        bool in = t < cnt;
        if (!__any_sync(FULLM, in)) break;
        bool valid = false;
        int ns = 0, nd = 0;
        if (in) {
            ns = map[srcP[t]];
            nd = map[dstP[t]];
            valid = (ns >= 0) && (nd >= 0);
        }
        unsigned m = __ballot_sync(FULLM, valid);
        if (m) {
            int leader = __ffs(m) - 1;
            int base = 0;
            if (lane == leader) base = atomicAdd(cntN, __popc(m));
            base = __shfl_sync(FULLM, base, leader);
            if (valid) {
                int off = __popc(m & ((1u << lane) - 1));
                srcN[base + off] = ns;
                dstN[base + off] = nd;
                atomicAdd(&deg[nd], 1);
            }
        }
    }
}

// block0 matmul: H[n,64] = X[n,3] @ W[3,64]; zeroes its stats slot
__global__ void k_mm0(const float* __restrict__ X, const float* __restrict__ W,
                      float* __restrict__ H, float* __restrict__ stats, int n) {
    if (blockIdx.x == 0 && threadIdx.x < 128) stats[threadIdx.x] = 0.f;
    int t = blockIdx.x * blockDim.x + threadIdx.x;
    if (t >= n * 16) return;
    int r = t >> 4, q = (t & 15) * 4;
    const float* xp = X + (long long)r * 3;
    float a0 = 0.f, a1 = 0.f, a2 = 0.f, a3 = 0.f;
    #pragma unroll
    for (int k = 0; k < 3; k++) {
        float xv = xp[k];
        a0 += xv * __ldg(&W[k * HID + q]);
        a1 += xv * __ldg(&W[k * HID + q + 1]);
        a2 += xv * __ldg(&W[k * HID + q + 2]);
        a3 += xv * __ldg(&W[k * HID + q + 3]);
    }
    reinterpret_cast<float4*>(H)[(long long)r * 16 + (q >> 2)] = make_float4(a0, a1, a2, a3);
}

// pooled matmul: H = (X[perm[r]] * sc[r]) @ W ; 4 rows x 4 cols per thread
__global__ void k_mm_pool(const float* __restrict__ X, const float* __restrict__ W,
                          const int* __restrict__ perm, const float* __restrict__ sc,
                          float* __restrict__ H, float* __restrict__ stats, int n) {
    __shared__ float sW[HID * HID];
    for (int i = threadIdx.x; i < HID * HID; i += blockDim.x) sW[i] = W[i];
    if (blockIdx.x == 0 && threadIdx.x < 128) stats[threadIdx.x] = 0.f;
    __syncthreads();
    int t = blockIdx.x * blockDim.x + threadIdx.x;
    int rg = t >> 4, cg = t & 15;
    if (rg * 4 >= n) return;
    const float* xp[4];
    float s[4];
    #pragma unroll
    for (int i = 0; i < 4; i++) {
        int r = rg * 4 + i;
        xp[i] = X + (long long)perm[r] * HID;
        s[i] = sc[r];
    }
    float acc[4][4];
    #pragma unroll
    for (int i = 0; i < 4; i++)
        #pragma unroll
        for (int j = 0; j < 4; j++) acc[i][j] = 0.f;
    for (int k = 0; k < HID; k++) {
        float4 w = reinterpret_cast<const float4*>(sW)[k * 16 + cg];
        #pragma unroll
        for (int i = 0; i < 4; i++) {
            float xv = xp[i][k] * s[i];
            acc[i][0] += xv * w.x; acc[i][1] += xv * w.y;
            acc[i][2] += xv * w.z; acc[i][3] += xv * w.w;
        }
    }
    #pragma unroll
    for (int i = 0; i < 4; i++)
        reinterpret_cast<float4*>(H)[(long long)(rg * 4 + i) * 16 + cg] =
            make_float4(acc[i][0], acc[i][1], acc[i][2], acc[i][3]);
}

// up-path matmul, residual unpool with FUSED BN+ReLU of the upsampled input:
// row = X[r] + (map[r]>=0 ? relu(a*Yup[map[r]] + b) : 0)
__global__ void k_mm_res_bn(const float* __restrict__ X, const float* __restrict__ Yup,
                            const int* __restrict__ map,
                            const float* __restrict__ gammaP, const float* __restrict__ betaP,
                            const float* __restrict__ statsP, float inv_np,
                            const float* __restrict__ W,
                            float* __restrict__ H, float* __restrict__ stats, int n) {
    __shared__ float sW[HID * HID];
    __shared__ float sA[HID], sB[HID];
    for (int i = threadIdx.x; i < HID * HID; i += blockDim.x) sW[i] = W[i];
    if (threadIdx.x < HID) {
        int c = threadIdx.x;
        float mu = statsP[c] * inv_np;
        float var = statsP[HID + c] * inv_np - mu * mu;
        float g = gammaP[c] * rsqrtf(var + BN_EPS);
        sA[c] = g;
        sB[c] = betaP[c] - g * mu;
    }
    if (blockIdx.x == 0 && threadIdx.x < 128) stats[threadIdx.x] = 0.f;
    __syncthreads();
    int t = blockIdx.x * blockDim.x + threadIdx.x;
    int rg = t >> 4, cg = t & 15;
    if (rg * 4 >= n) return;
    const float* xp[4];
    const float* up[4];
    #pragma unroll
    for (int i = 0; i < 4; i++) {
        int r = rg * 4 + i;
        xp[i] = X + (long long)r * HID;
        int m = map[r];
        up[i] = (m >= 0) ? (Yup + (long long)m * HID) : nullptr;
    }
    float acc[4][4];
    #pragma unroll
    for (int i = 0; i < 4; i++)
        #pragma unroll
        for (int j = 0; j < 4; j++) acc[i][j] = 0.f;
    for (int k = 0; k < HID; k++) {
        float4 w = reinterpret_cast<const float4*>(sW)[k * 16 + cg];
        float a = sA[k], b = sB[k];
        #pragma unroll
        for (int i = 0; i < 4; i++) {
            float xv = xp[i][k];
            if (up[i]) xv += fmaxf(a * up[i][k] + b, 0.f);
            acc[i][0] += xv * w.x; acc[i][1] += xv * w.y;
            acc[i][2] += xv * w.z; acc[i][3] += xv * w.w;
        }
    }
    #pragma unroll
    for (int i = 0; i < 4; i++)
        reinterpret_cast<float4*>(H)[(long long)(rg * 4 + i) * 16 + cg] =
            make_float4(acc[i][0], acc[i][1], acc[i][2], acc[i][3]);
}

// warp per dst row (grid-stride): Y[d] = sum cf*H[s] + fill*dinv[d]^2*H[d]; BN stats
__global__ void k_agg_bn(const int* __restrict__ rs, const int* __restrict__ csr,
                         const float* __restrict__ dinv, const float* __restrict__ H,
                         float* __restrict__ Y, float* __restrict__ stats,
                         float fill, int n) {
    __shared__ float sh[128];
    if (threadIdx.x < 128) sh[threadIdx.x] = 0.f;
    __syncthreads();
    int lane = threadIdx.x & 31;
    int w = (blockIdx.x * blockDim.x + threadIdx.x) >> 5;
    int nw = (gridDim.x * blockDim.x) >> 5;
    float s0 = 0.f, s1 = 0.f, q0 = 0.f, q1 = 0.f;
    for (int d = w; d < n; d += nw) {
        int r0 = rs[d], r1 = rs[d + 1];
        float dd = dinv[d];
        float a0 = 0.f, a1 = 0.f;
        int j = r0;
        for (; j + 2 <= r1; j += 2) {
            int sA = csr[j], sB = csr[j + 1];
            float cfA = dinv[sA] * dd;
            float cfB = dinv[sB] * dd;
            float2 hA = reinterpret_cast<const float2*>(H)[(long long)sA * 32 + lane];
            float2 hB = reinterpret_cast<const float2*>(H)[(long long)sB * 32 + lane];
            a0 += cfA * hA.x + cfB * hB.x;
            a1 += cfA * hA.y + cfB * hB.y;
        }
        if (j < r1) {
            int sA = csr[j];
            float cfA = dinv[sA] * dd;
            float2 hA = reinterpret_cast<const float2*>(H)[(long long)sA * 32 + lane];
            a0 += cfA * hA.x;
            a1 += cfA * hA.y;
        }
        float2 hd = reinterpret_cast<const float2*>(H)[(long long)d * 32 + lane];
        float sf = fill * dd * dd;
        float y0 = a0 + sf * hd.x;
        float y1 = a1 + sf * hd.y;
        reinterpret_cast<float2*>(Y)[(long long)d * 32 + lane] = make_float2(y0, y1);
        s0 += y0; s1 += y1; q0 += y0 * y0; q1 += y1 * y1;
    }
    atomicAdd(&sh[2 * lane],      s0);
    atomicAdd(&sh[2 * lane + 1],  s1);
    atomicAdd(&sh[64 + 2 * lane], q0);
    atomicAdd(&sh[65 + 2 * lane], q1);
    __syncthreads();
    if (threadIdx.x < 128) atomicAdd(&stats[threadIdx.x], sh[threadIdx.x]);
}

// fused BN + ReLU + topk-score + idx init + next-level map/deg init
__global__ void k_bn_score(const float* __restrict__ Y, const float* __restrict__ gamma,
                           const float* __restrict__ beta, const float* __restrict__ stats,
                           float* __restrict__ Xo, const float* __restrict__ pw,
                           float* __restrict__ keys, int* __restrict__ idx,
                           int* __restrict__ map, int* __restrict__ deg, int n) {
    int gtid = blockIdx.x * blockDim.x + threadIdx.x;
    int stride = gridDim.x * blockDim.x;
    int lane = threadIdx.x & 31;
    float inv_n = 1.f / (float)n;
    float pa = pw[lane], pb = pw[lane + 32];
    float nv = pa * pa + pb * pb;
    #pragma unroll
    for (int o = 16; o > 0; o >>= 1) nv += __shfl_xor_sync(FULLM, nv, o);
    float rn = rsqrtf(nv);
    float mu0 = stats[lane] * inv_n;
    float var0 = stats[HID + lane] * inv_n - mu0 * mu0;
    float rs0_ = gamma[lane] * rsqrtf(var0 + BN_EPS);
    float b0 = beta[lane];
    float mu1 = stats[lane + 32] * inv_n;
    float var1 = stats[HID + lane + 32] * inv_n - mu1 * mu1;
    float rs1_ = gamma[lane + 32] * rsqrtf(var1 + BN_EPS);
    float b1 = beta[lane + 32];
    for (int r = gtid >> 5; r < n; r += stride >> 5) {
        float y0 = Y[(long long)r * HID + lane];
        float y1 = Y[(long long)r * HID + lane + 32];
        float x0 = fmaxf(rs0_ * (y0 - mu0) + b0, 0.f);
        float x1 = fmaxf(rs1_ * (y1 - mu1) + b1, 0.f);
        Xo[(long long)r * HID + lane] = x0;
        Xo[(long long)r * HID + lane + 32] = x1;
        float v = x0 * pa + x1 * pb;
        #pragma unroll
        for (int o = 16; o > 0; o >>= 1) v += __shfl_xor_sync(FULLM, v, o);
        if (lane == 0) {
            keys[r] = fmaxf(v * rn, 0.f);
            idx[r] = r;
        }
    }
    for (int t = gtid; t < n; t += stride) {
        map[t] = -1;
        deg[t] = 0;
    }
}

// final 1-channel conv matmul with fused residual unpool + BN+ReLU of upsample
__global__ void k_mm1_res_bn(const float* __restrict__ X, const float* __restrict__ Yup,
                             const int* __restrict__ map,
                             const float* __restrict__ gammaP, const float* __restrict__ betaP,
                             const float* __restrict__ statsP, float inv_np,
                             const float* __restrict__ W, float* __restrict__ h, int n) {
    __shared__ float sW[HID], sA[HID], sB[HID];
    if (threadIdx.x < HID) {
        int c = threadIdx.x;
        sW[c] = W[c];
        float mu = statsP[c] * inv_np;
        float var = statsP[HID + c] * inv_np - mu * mu;
        float g = gammaP[c] * rsqrtf(var + BN_EPS);
        sA[c] = g;
        sB[c] = betaP[c] - g * mu;
    }
    __syncthreads();
    int r = blockIdx.x * blockDim.x + threadIdx.x;
    if (r >= n) return;
    int m = map[r];
    const float* xp = X + (long long)r * HID;
    const float* up = (m >= 0) ? (Yup + (long long)m * HID) : nullptr;
    float acc = 0.f;
    #pragma unroll
    for (int k = 0; k < HID; k++) {
        float xv = xp[k];
        if (up) xv += fmaxf(sA[k] * up[k] + sB[k], 0.f);
        acc += xv * sW[k];
    }
    h[r] = acc;
}

// out[d] = sigmoid(dinv[d]*sum(dinv[s]h[s]) + dinv[d]^2 h[d])
__global__ void k_csr_final(const int* __restrict__ rs, const int* __restrict__ csr,
                            const float* __restrict__ dinv, const float* __restrict__ h,
                            float* __restrict__ out, int n) {
    int lane = threadIdx.x & 31;
    int w = (blockIdx.x * blockDim.x + threadIdx.x) >> 5;
    int nw = (gridDim.x * blockDim.x) >> 5;
    for (int d = w; d < n; d += nw) {
        int r0 = rs[d], r1 = rs[d + 1];
        float acc = 0.f;
        for (int j = r0 + lane; j < r1; j += 32) {
            int s = csr[j];
            acc += dinv[s] * h[s];
        }
        #pragma unroll
        for (int o = 16; o > 0; o >>= 1) acc += __shfl_xor_sync(FULLM, acc, o);
        if (lane == 0) {
            float dd = dinv[d];
            float v = dd * acc + dd * dd * h[d];
            out[d] = 1.f / (1.f + expf(-v));
        }
    }
}

// ------------------------------- host side ---------------------------------
static inline int nblk(long long n) { return (int)((n + TPB - 1) / TPB); }
static inline int gridA(int n) { int g = (n + 7) / 8; return g > 2048 ? 2048 : g; }

struct DevPtrs {
    float *X0, *X1, *X2, *H, *Y, *YD3, *YU0, *YU1;
    int *deg, *cursor, *rs0, *rs1, *rs2, *rs3;
    float *dinv0_2, *dinv0_1, *dinv1, *dinv2, *dinv3;
    int *csr0, *csr1, *csr2, *csr3;
    int *src1, *dst1, *src2, *dst2, *src3, *dst3, *cnt;
    float *keys, *keysOut, *stats, *h1;
    int *idx, *perm0, *perm1, *perm2, *map0, *map1, *map2;
    void* cubtmp;
};

#define GETP(sym, field, type) { void* q; cudaGetSymbolAddress(&q, sym); p.field = (type)q; }

static void get_ptrs(DevPtrs& p) {
    GETP(g_X0, X0, float*) GETP(g_X1, X1, float*) GETP(g_X2, X2, float*)
    GETP(g_H, H, float*) GETP(g_Y, Y, float*)
    GETP(g_YD3, YD3, float*) GETP(g_YU0, YU0, float*) GETP(g_YU1, YU1, float*)
    GETP(g_deg, deg, int*) GETP(g_cursor, cursor, int*)
    GETP(g_rs0, rs0, int*) GETP(g_rs1, rs1, int*) GETP(g_rs2, rs2, int*) GETP(g_rs3, rs3, int*)
    GETP(g_dinv0_2, dinv0_2, float*) GETP(g_dinv0_1, dinv0_1, float*)
    GETP(g_dinv1, dinv1, float*) GETP(g_dinv2, dinv2, float*) GETP(g_dinv3, dinv3, float*)
    GETP(g_csr0, csr0, int*) GETP(g_csr1, csr1, int*) GETP(g_csr2, csr2, int*) GETP(g_csr3, csr3, int*)
    GETP(g_src1, src1, int*) GETP(g_dst1, dst1, int*)
    GETP(g_src2, src2, int*) GETP(g_dst2, dst2, int*)
    GETP(g_src3, src3, int*) GETP(g_dst3, dst3, int*)
    GETP(g_cnt, cnt, int*)
    GETP(g_keys, keys, float*) GETP(g_keysOut, keysOut, float*)
    GETP(g_statsAll, stats, float*) GETP(g_h1, h1, float*)
    GETP(g_idx, idx, int*)
    GETP(g_perm0, perm0, int*) GETP(g_perm1, perm1, int*) GETP(g_perm2, perm2, int*)
    GETP(g_map0, map0, int*) GETP(g_map1, map1, int*) GETP(g_map2, map2, int*)
    GETP(g_cubtmp, cubtmp, void*)
}

static cudaStream_t s_side;
static cudaEvent_t  s_evF[5], s_evJ[5];
static bool s_init = false;

static void fork_side(int i) {
    cudaEventRecord(s_evF[i], 0);
    cudaStreamWaitEvent(s_side, s_evF[i], 0);
}
static void join_side(int i) {
    cudaEventRecord(s_evJ[i], s_side);
    cudaStreamWaitEvent(0, s_evJ[i], 0);
}

// side-stream CSR build: fused scan/prep + scatter
static void csr_chain(const DevPtrs& p, const int* srcC, const int* dstC,
                      const int* cntp, int nfix, int n, int* rs, int* csr,
                      float* dinvA, float fillA, float* dinvB, float fillB) {
    k_scanprep<<<1, 1024, 0, s_side>>>(p.deg, rs, p.cursor, dinvA, fillA, dinvB, fillB, n);
    k_scatter<<<GRIDE, TPB, 0, s_side>>>(srcC, dstC, p.cursor, csr, cntp, nfix);
}

static void radix_sort(const DevPtrs& p, int* permOut, int n) {
    size_t tb = 0;
    cub::DeviceRadixSort::SortPairsDescending(nullptr, tb, p.keys, p.keysOut,
                                              p.idx, permOut, n, 0, 32, (cudaStream_t)0);
    cub::DeviceRadixSort::SortPairsDescending(p.cubtmp, tb, p.keys, p.keysOut,
                                              p.idx, permOut, n, 0, 32, (cudaStream_t)0);
}

extern "C" void kernel_launch(void* const* d_in, const int* in_sizes, int n_in,
                              void* d_out, int out_size) {
    if (!s_init) {   // first call is the uncaptured correctness run
        cudaStreamCreateWithFlags(&s_side, cudaStreamNonBlocking);
        for (int i = 0; i < 5; i++) {
            cudaEventCreateWithFlags(&s_evF[i], cudaEventDisableTiming);
            cudaEventCreateWithFlags(&s_evJ[i], cudaEventDisableTiming);
        }
        s_init = true;
    }

    const float* x_in = (const float*)d_in[0];
    const int* ei     = (const int*)d_in[1];
    const int* src0 = ei;
    const int* dst0 = ei + cNE;
    const float* Wd[4] = {(const float*)d_in[2],  (const float*)d_in[5],
                          (const float*)d_in[8],  (const float*)d_in[11]};
    const float* gd[4] = {(const float*)d_in[3],  (const float*)d_in[6],
                          (const float*)d_in[9],  (const float*)d_in[12]};
    const float* bd[4] = {(const float*)d_in[4],  (const float*)d_in[7],
                          (const float*)d_in[10], (const float*)d_in[13]};
    const float* pw[3] = {(const float*)d_in[14], (const float*)d_in[15],
                          (const float*)d_in[16]};
    const float* Wu[2] = {(const float*)d_in[17], (const float*)d_in[20]};
    const float* gu[2] = {(const float*)d_in[18], (const float*)d_in[21]};
    const float* bu[2] = {(const float*)d_in[19], (const float*)d_in[22]};
    const float* Wout  = (const float*)d_in[23];

    DevPtrs p;
    get_ptrs(p);
    float* S[6];
    for (int i = 0; i < 6; i++) S[i] = p.stats + i * 128;

    // ===== phase 0: block0 matmul || level-0 CSR build =====
    fork_side(0);
    k_zeroi<<<nblk(cN0 + 1), TPB, 0, s_side>>>(p.deg, cN0 + 1);
    k_hist0<<<GRIDE, TPB, 0, s_side>>>(dst0, p.deg);
    csr_chain(p, src0, dst0, nullptr, cNE, cN0, p.rs0, p.csr0,
              p.dinv0_2, 2.0f, p.dinv0_1, 1.0f);
    k_mm0<<<nblk((long long)cN0 * 16), TPB>>>(x_in, Wd[0], p.H, S[0], cN0);
    join_side(0);
    k_agg_bn<<<gridA(cN0), TPB>>>(p.rs0, p.csr0, p.dinv0_2, p.H, p.Y, S[0], 2.0f, cN0);
    k_bn_score<<<2048, TPB>>>(p.Y, gd[0], bd[0], S[0], p.X0, pw[0],
                              p.keys, p.idx, p.map0, p.deg, cN0);

    // ===== pool 0 + block 1 =====
    radix_sort(p, p.perm0, cN0);
    fork_side(1);
    k_mapset<<<nblk(cN1), TPB, 0, s_side>>>(p.map0, p.perm0, cN1, &p.cnt[0]);
    k_remap_hist<<<GRIDE, TPB, 0, s_side>>>(src0, dst0, p.map0, p.src1, p.dst1,
                                            &p.cnt[0], p.deg, nullptr, cNE);
    csr_chain(p, p.src1, p.dst1, &p.cnt[0], 0, cN1, p.rs1, p.csr1,
              p.dinv1, 2.0f, nullptr, 0.f);
    k_mm_pool<<<nblk((long long)cN1 * 4), TPB>>>(p.X0, Wd[1], p.perm0, p.keysOut,
                                                 p.H, S[1], cN1);
    join_side(1);
    k_agg_bn<<<gridA(cN1), TPB>>>(p.rs1, p.csr1, p.dinv1, p.H, p.Y, S[1], 2.0f, cN1);
    k_bn_score<<<1024, TPB>>>(p.Y, gd[1], bd[1], S[1], p.X1, pw[1],
                              p.keys, p.idx, p.map1, p.deg, cN1);

    // ===== pool 1 + block 2 =====
    radix_sort(p, p.perm1, cN1);
    fork_side(2);
    k_mapset<<<nblk(cN2), TPB, 0, s_side>>>(p.map1, p.perm1, cN2, &p.cnt[1]);
    k_remap_hist<<<GRIDE, TPB, 0, s_side>>>(p.src1, p.dst1, p.map1, p.src2, p.dst2,
                                            &p.cnt[1], p.deg, &p.cnt[0], 0);
    csr_chain(p, p.src2, p.dst2, &p.cnt[1], 0, cN2, p.rs2, p.csr2,
              p.dinv2, 2.0f, nullptr, 0.f);
    k_mm_pool<<<nblk((long long)cN2 * 4), TPB>>>(p.X1, Wd[2], p.perm1, p.keysOut,
                                                 p.H, S[2], cN2);
    join_side(2);
    k_agg_bn<<<gridA(cN2), TPB>>>(p.rs2, p.csr2, p.dinv2, p.H, p.Y, S[2], 2.0f, cN2);
    k_bn_score<<<512, TPB>>>(p.Y, gd[2], bd[2], S[2], p.X2, pw[2],
                             p.keys, p.idx, p.map2, p.deg, cN2);

    // ===== pool 2 + block 3 =====
    radix_sort(p, p.perm2, cN2);
    fork_side(3);
    k_mapset<<<nblk(cN3), TPB, 0, s_side>>>(p.map2, p.perm2, cN3, &p.cnt[2]);
    k_remap_hist<<<GRIDE, TPB, 0, s_side>>>(p.src2, p.dst2, p.map2, p.src3, p.dst3,
                                            &p.cnt[2], p.deg, &p.cnt[1], 0);
    csr_chain(p, p.src3, p.dst3, &p.cnt[2], 0, cN3, p.rs3, p.csr3,
              p.dinv3, 2.0f, nullptr, 0.f);
    k_mm_pool<<<nblk((long long)cN3 * 4), TPB>>>(p.X2, Wd[3], p.perm2, p.keysOut,
                                                 p.H, S[3], cN3);
    join_side(3);
    k_agg_bn<<<gridA(cN3), TPB>>>(p.rs3, p.csr3, p.dinv3, p.H, p.YD3, S[3], 2.0f, cN3);

    // ===== up path (BN of previous block fused into each consumer) =====
    // up0: rows = X2 + relu(bn(YD3[map2])), conv over level-2 CSR
    k_mm_res_bn<<<nblk((long long)cN2 * 4), TPB>>>(p.X2, p.YD3, p.map2,
                                                   gd[3], bd[3], S[3], 1.f / cN3,
                                                   Wu[0], p.H, S[4], cN2);
    k_agg_bn<<<gridA(cN2), TPB>>>(p.rs2, p.csr2, p.dinv2, p.H, p.YU0, S[4], 2.0f, cN2);

    // up1: rows = X1 + relu(bn(YU0[map1])), conv over level-1 CSR
    k_mm_res_bn<<<nblk((long long)cN1 * 4), TPB>>>(p.X1, p.YU0, p.map1,
                                                   gu[0], bu[0], S[4], 1.f / cN2,
                                                   Wu[1], p.H, S[5], cN1);
    k_agg_bn<<<gridA(cN1), TPB>>>(p.rs1, p.csr1, p.dinv1, p.H, p.YU1, S[5], 2.0f, cN1);

    // final: rows = X0 + relu(bn(YU1[map0])), 1-ch conv (fill=1) + sigmoid
    k_mm1_res_bn<<<nblk(cN0), TPB>>>(p.X0, p.YU1, p.map0,
                                     gu[1], bu[1], S[5], 1.f / cN1,
                                     Wout, p.h1, cN0);
    k_csr_final<<<2048, TPB>>>(p.rs0, p.csr0, p.dinv0_1, p.h1, (float*)d_out, cN0);
}

// round 5
// speedup vs baseline: 1.5060x; 1.5060x over previous
#include <cuda_runtime.h>
#include <cub/cub.cuh>

// ---------------------------------------------------------------------------
// Graph U-Net forward — CSR aggregation, fused BN-in-consumer, cub scan,
// 2-stream overlap.
// ---------------------------------------------------------------------------
#define cN0 80000
#define cN1 40000
#define cN2 20000
#define cN3 10000
#define cNE 1280000
#define HID 64
#define BN_EPS 1e-5f
#define TPB 256
#define GRIDE 1184
#define FULLM 0xffffffffu

// ------------------------- static device scratch ---------------------------
__device__ __align__(16) float g_X0[cN0 * HID];
__device__ __align__(16) float g_X1[cN1 * HID];
__device__ __align__(16) float g_X2[cN2 * HID];
__device__ __align__(16) float g_H [cN0 * HID];
__device__ __align__(16) float g_Y [cN0 * HID];   // down-path agg output (transient)
__device__ __align__(16) float g_YD3[cN3 * HID];  // block3 agg output (persists)
__device__ __align__(16) float g_YU0[cN2 * HID];  // up0 agg output (persists)
__device__ __align__(16) float g_YU1[cN1 * HID];  // up1 agg output (persists)
__device__ int   g_deg[cN0 + 1];
__device__ int   g_cursor[cN0];
__device__ int   g_rs0[cN0 + 1], g_rs1[cN1 + 1], g_rs2[cN2 + 1], g_rs3[cN3 + 1];
__device__ float g_dinv0_2[cN0], g_dinv0_1[cN0];
__device__ float g_dinv1[cN1], g_dinv2[cN2], g_dinv3[cN3];
__device__ int   g_csr0[cNE], g_csr1[cNE], g_csr2[cNE], g_csr3[cNE];
__device__ int   g_src1[cNE], g_dst1[cNE];
__device__ int   g_src2[cNE], g_dst2[cNE];
__device__ int   g_src3[cNE], g_dst3[cNE];
__device__ int   g_cnt[4];
__device__ float g_keys[cN0], g_keysOut[cN0];
__device__ int   g_idx[cN0];
__device__ int   g_perm0[cN0], g_perm1[cN1], g_perm2[cN2];
__device__ int   g_map0[cN0], g_map1[cN1], g_map2[cN2];
__device__ float g_statsAll[6 * 128];             // per-block BN stat slots
__device__ float g_h1[cN0];
__device__ __align__(256) unsigned char g_cubtmp[16 * 1024 * 1024];

// ------------------------------- kernels -----------------------------------
__global__ void k_zeroi(int* __restrict__ p, int n) {
    int t = blockIdx.x * blockDim.x + threadIdx.x;
    if (t < n) p[t] = 0;
}

__global__ void k_hist0(const int* __restrict__ dst, int* __restrict__ deg) {
    for (int t = blockIdx.x * blockDim.x + threadIdx.x; t < cNE; t += gridDim.x * blockDim.x)
        atomicAdd(&deg[dst[t]], 1);
}

// cursor[t]=rs[t]; dinv from CSR row extents (degree)
__global__ void k_prep(const int* __restrict__ rs, int* __restrict__ cursor,
                       float* __restrict__ dinvA, float fillA,
                       float* __restrict__ dinvB, float fillB, int n) {
    int t = blockIdx.x * blockDim.x + threadIdx.x;
    if (t >= n) return;
    int r0 = rs[t], r1 = rs[t + 1];
    cursor[t] = r0;
    float d = (float)(r1 - r0);
    dinvA[t] = rsqrtf(d + fillA);
    if (dinvB) dinvB[t] = rsqrtf(d + fillB);
}

__global__ void k_scatter(const int* __restrict__ srcC, const int* __restrict__ dstC,
                          int* __restrict__ cursor, int* __restrict__ csr,
                          const int* __restrict__ cntp, int nfix) {
    int cnt = cntp ? *cntp : nfix;
    for (int t = blockIdx.x * blockDim.x + threadIdx.x; t < cnt; t += gridDim.x * blockDim.x) {
        int pos = atomicAdd(&cursor[dstC[t]], 1);
        csr[pos] = srcC[t];
    }
}

__global__ void k_mapset(int* __restrict__ map, const int* __restrict__ perm,
                         int k, int* __restrict__ cntZ) {
    int t = blockIdx.x * blockDim.x + threadIdx.x;
    if (t == 0) *cntZ = 0;
    if (t < k) map[perm[t]] = t;
}

// compact remap + dst-degree histogram; warp-aggregated counter pushes
__global__ void k_remap_hist(const int* __restrict__ srcP, const int* __restrict__ dstP,
                             const int* __restrict__ map, int* __restrict__ srcN,
                             int* __restrict__ dstN, int* __restrict__ cntN,
                             int* __restrict__ deg, const int* __restrict__ cntp, int nfix) {
    int cnt = cntp ? *cntp : nfix;
    int lane = threadIdx.x & 31;
    int stride = gridDim.x * blockDim.x;
    for (int t = blockIdx.x * blockDim.x + threadIdx.x;; t += stride) {
        bool in = t < cnt;
        if (!__any_sync(FULLM, in)) break;
        bool valid = false;
        int ns = 0, nd = 0;
        if (in) {
            ns = map[srcP[t]];
            nd = map[dstP[t]];
            valid = (ns >= 0) && (nd >= 0);
        }
        unsigned m = __ballot_sync(FULLM, valid);
        if (m) {
            int leader = __ffs(m) - 1;
            int base = 0;
            if (lane == leader) base = atomicAdd(cntN, __popc(m));
            base = __shfl_sync(FULLM, base, leader);
            if (valid) {
                int off = __popc(m & ((1u << lane) - 1));
                srcN[base + off] = ns;
                dstN[base + off] = nd;
                atomicAdd(&deg[nd], 1);
            }
        }
    }
}

// block0 matmul: H[n,64] = X[n,3] @ W[3,64]; zeroes its stats slot
__global__ void k_mm0(const float* __restrict__ X, const float* __restrict__ W,
                      float* __restrict__ H, float* __restrict__ stats, int n) {
    if (blockIdx.x == 0 && threadIdx.x < 128) stats[threadIdx.x] = 0.f;
    int t = blockIdx.x * blockDim.x + threadIdx.x;
    if (t >= n * 16) return;
    int r = t >> 4, q = (t & 15) * 4;
    const float* xp = X + (long long)r * 3;
    float a0 = 0.f, a1 = 0.f, a2 = 0.f, a3 = 0.f;
    #pragma unroll
    for (int k = 0; k < 3; k++) {
        float xv = xp[k];
        a0 += xv * __ldg(&W[k * HID + q]);
        a1 += xv * __ldg(&W[k * HID + q + 1]);
        a2 += xv * __ldg(&W[k * HID + q + 2]);
        a3 += xv * __ldg(&W[k * HID + q + 3]);
    }
    reinterpret_cast<float4*>(H)[(long long)r * 16 + (q >> 2)] = make_float4(a0, a1, a2, a3);
}

// pooled matmul: H = (X[perm[r]] * sc[r]) @ W ; 4 rows x 4 cols per thread
__global__ void k_mm_pool(const float* __restrict__ X, const float* __restrict__ W,
                          const int* __restrict__ perm, const float* __restrict__ sc,
                          float* __restrict__ H, float* __restrict__ stats, int n) {
    __shared__ float sW[HID * HID];
    for (int i = threadIdx.x; i < HID * HID; i += blockDim.x) sW[i] = W[i];
    if (blockIdx.x == 0 && threadIdx.x < 128) stats[threadIdx.x] = 0.f;
    __syncthreads();
    int t = blockIdx.x * blockDim.x + threadIdx.x;
    int rg = t >> 4, cg = t & 15;
    if (rg * 4 >= n) return;
    const float* xp[4];
    float s[4];
    #pragma unroll
    for (int i = 0; i < 4; i++) {
        int r = rg * 4 + i;
        xp[i] = X + (long long)perm[r] * HID;
        s[i] = sc[r];
    }
    float acc[4][4];
    #pragma unroll
    for (int i = 0; i < 4; i++)
        #pragma unroll
        for (int j = 0; j < 4; j++) acc[i][j] = 0.f;
    for (int k = 0; k < HID; k++) {
        float4 w = reinterpret_cast<const float4*>(sW)[k * 16 + cg];
        #pragma unroll
        for (int i = 0; i < 4; i++) {
            float xv = xp[i][k] * s[i];
            acc[i][0] += xv * w.x; acc[i][1] += xv * w.y;
            acc[i][2] += xv * w.z; acc[i][3] += xv * w.w;
        }
    }
    #pragma unroll
    for (int i = 0; i < 4; i++)
        reinterpret_cast<float4*>(H)[(long long)(rg * 4 + i) * 16 + cg] =
            make_float4(acc[i][0], acc[i][1], acc[i][2], acc[i][3]);
}

// up-path matmul, residual unpool with FUSED BN+ReLU of the upsampled input:
// row = X[r] + (map[r]>=0 ? relu(a*Yup[map[r]] + b) : 0)
__global__ void k_mm_res_bn(const float* __restrict__ X, const float* __restrict__ Yup,
                            const int* __restrict__ map,
                            const float* __restrict__ gammaP, const float* __restrict__ betaP,
                            const float* __restrict__ statsP, float inv_np,
                            const float* __restrict__ W,
                            float* __restrict__ H, float* __restrict__ stats, int n) {
    __shared__ float sW[HID * HID];
    __shared__ float sA[HID], sB[HID];
    for (int i = threadIdx.x; i < HID * HID; i += blockDim.x) sW[i] = W[i];
    if (threadIdx.x < HID) {
        int c = threadIdx.x;
        float mu = statsP[c] * inv_np;
        float var = statsP[HID + c] * inv_np - mu * mu;
        float g = gammaP[c] * rsqrtf(var + BN_EPS);
        sA[c] = g;
        sB[c] = betaP[c] - g * mu;
    }
    if (blockIdx.x == 0 && threadIdx.x < 128) stats[threadIdx.x] = 0.f;
    __syncthreads();
    int t = blockIdx.x * blockDim.x + threadIdx.x;
    int rg = t >> 4, cg = t & 15;
    if (rg * 4 >= n) return;
    const float* xp[4];
    const float* up[4];
    #pragma unroll
    for (int i = 0; i < 4; i++) {
        int r = rg * 4 + i;
        xp[i] = X + (long long)r * HID;
        int m = map[r];
        up[i] = (m >= 0) ? (Yup + (long long)m * HID) : nullptr;
    }
    float acc[4][4];
    #pragma unroll
    for (int i = 0; i < 4; i++)
        #pragma unroll
        for (int j = 0; j < 4; j++) acc[i][j] = 0.f;
    for (int k = 0; k < HID; k++) {
        float4 w = reinterpret_cast<const float4*>(sW)[k * 16 + cg];
        float a = sA[k], b = sB[k];
        #pragma unroll
        for (int i = 0; i < 4; i++) {
            float xv = xp[i][k];
            if (up[i]) xv += fmaxf(a * up[i][k] + b, 0.f);
            acc[i][0] += xv * w.x; acc[i][1] += xv * w.y;
            acc[i][2] += xv * w.z; acc[i][3] += xv * w.w;
        }
    }
    #pragma unroll
    for (int i = 0; i < 4; i++)
        reinterpret_cast<float4*>(H)[(long long)(rg * 4 + i) * 16 + cg] =
            make_float4(acc[i][0], acc[i][1], acc[i][2], acc[i][3]);
}

// warp per dst row (grid-stride): Y[d] = sum cf*H[s] + fill*dinv[d]^2*H[d]; BN stats
__global__ void k_agg_bn(const int* __restrict__ rs, const int* __restrict__ csr,
                         const float* __restrict__ dinv, const float* __restrict__ H,
                         float* __restrict__ Y, float* __restrict__ stats,
                         float fill, int n) {
    __shared__ float sh[128];
    if (threadIdx.x < 128) sh[threadIdx.x] = 0.f;
    __syncthreads();
    int lane = threadIdx.x & 31;
    int w = (blockIdx.x * blockDim.x + threadIdx.x) >> 5;
    int nw = (gridDim.x * blockDim.x) >> 5;
    float s0 = 0.f, s1 = 0.f, q0 = 0.f, q1 = 0.f;
    for (int d = w; d < n; d += nw) {
        int r0 = rs[d], r1 = rs[d + 1];
        float dd = dinv[d];
        float a0 = 0.f, a1 = 0.f;
        int j = r0;
        for (; j + 2 <= r1; j += 2) {
            int sA = csr[j], sB = csr[j + 1];
            float cfA = dinv[sA] * dd;
            float cfB = dinv[sB] * dd;
            float2 hA = reinterpret_cast<const float2*>(H)[(long long)sA * 32 + lane];
            float2 hB = reinterpret_cast<const float2*>(H)[(long long)sB * 32 + lane];
            a0 += cfA * hA.x + cfB * hB.x;
            a1 += cfA * hA.y + cfB * hB.y;
        }
        if (j < r1) {
            int sA = csr[j];
            float cfA = dinv[sA] * dd;
            float2 hA = reinterpret_cast<const float2*>(H)[(long long)sA * 32 + lane];
            a0 += cfA * hA.x;
            a1 += cfA * hA.y;
        }
        float2 hd = reinterpret_cast<const float2*>(H)[(long long)d * 32 + lane];
        float sf = fill * dd * dd;
        float y0 = a0 + sf * hd.x;
        float y1 = a1 + sf * hd.y;
        reinterpret_cast<float2*>(Y)[(long long)d * 32 + lane] = make_float2(y0, y1);
        s0 += y0; s1 += y1; q0 += y0 * y0; q1 += y1 * y1;
    }
    atomicAdd(&sh[2 * lane],      s0);
    atomicAdd(&sh[2 * lane + 1],  s1);
    atomicAdd(&sh[64 + 2 * lane], q0);
    atomicAdd(&sh[65 + 2 * lane], q1);
    __syncthreads();
    if (threadIdx.x < 128) atomicAdd(&stats[threadIdx.x], sh[threadIdx.x]);
}

// fused BN + ReLU + topk-score + idx init + next-level map/deg init
__global__ void k_bn_score(const float* __restrict__ Y, const float* __restrict__ gamma,
                           const float* __restrict__ beta, const float* __restrict__ stats,
                           float* __restrict__ Xo, const float* __restrict__ pw,
                           float* __restrict__ keys, int* __restrict__ idx,
                           int* __restrict__ map, int* __restrict__ deg, int n) {
    int gtid = blockIdx.x * blockDim.x + threadIdx.x;
    int stride = gridDim.x * blockDim.x;
    int lane = threadIdx.x & 31;
    float inv_n = 1.f / (float)n;
    float pa = pw[lane], pb = pw[lane + 32];
    float nv = pa * pa + pb * pb;
    #pragma unroll
    for (int o = 16; o > 0; o >>= 1) nv += __shfl_xor_sync(FULLM, nv, o);
    float rn = rsqrtf(nv);
    float mu0 = stats[lane] * inv_n;
    float var0 = stats[HID + lane] * inv_n - mu0 * mu0;
    float rs0_ = gamma[lane] * rsqrtf(var0 + BN_EPS);
    float b0 = beta[lane];
    float mu1 = stats[lane + 32] * inv_n;
    float var1 = stats[HID + lane + 32] * inv_n - mu1 * mu1;
    float rs1_ = gamma[lane + 32] * rsqrtf(var1 + BN_EPS);
    float b1 = beta[lane + 32];
    for (int r = gtid >> 5; r < n; r += stride >> 5) {
        float y0 = Y[(long long)r * HID + lane];
        float y1 = Y[(long long)r * HID + lane + 32];
        float x0 = fmaxf(rs0_ * (y0 - mu0) + b0, 0.f);
        float x1 = fmaxf(rs1_ * (y1 - mu1) + b1, 0.f);
        Xo[(long long)r * HID + lane] = x0;
        Xo[(long long)r * HID + lane + 32] = x1;
        float v = x0 * pa + x1 * pb;
        #pragma unroll
        for (int o = 16; o > 0; o >>= 1) v += __shfl_xor_sync(FULLM, v, o);
        if (lane == 0) {
            keys[r] = fmaxf(v * rn, 0.f);
            idx[r] = r;
        }
    }
    for (int t = gtid; t < n; t += stride) {
        map[t] = -1;
        deg[t] = 0;
    }
}

// final 1-channel conv matmul with fused residual unpool + BN+ReLU of upsample
__global__ void k_mm1_res_bn(const float* __restrict__ X, const float* __restrict__ Yup,
                             const int* __restrict__ map,
                             const float* __restrict__ gammaP, const float* __restrict__ betaP,
                             const float* __restrict__ statsP, float inv_np,
                             const float* __restrict__ W, float* __restrict__ h, int n) {
    __shared__ float sW[HID], sA[HID], sB[HID];
    if (threadIdx.x < HID) {
        int c = threadIdx.x;
        sW[c] = W[c];
        float mu = statsP[c] * inv_np;
        float var = statsP[HID + c] * inv_np - mu * mu;
        float g = gammaP[c] * rsqrtf(var + BN_EPS);
        sA[c] = g;
        sB[c] = betaP[c] - g * mu;
    }
    __syncthreads();
    int r = blockIdx.x * blockDim.x + threadIdx.x;
    if (r >= n) return;
    int m = map[r];
    const float* xp = X + (long long)r * HID;
    const float* up = (m >= 0) ? (Yup + (long long)m * HID) : nullptr;
    float acc = 0.f;
    #pragma unroll
    for (int k = 0; k < HID; k++) {
        float xv = xp[k];
        if (up) xv += fmaxf(sA[k] * up[k] + sB[k], 0.f);
        acc += xv * sW[k];
    }
    h[r] = acc;
}

// out[d] = sigmoid(dinv[d]*sum(dinv[s]h[s]) + dinv[d]^2 h[d])
__global__ void k_csr_final(const int* __restrict__ rs, const int* __restrict__ csr,
                            const float* __restrict__ dinv, const float* __restrict__ h,
                            float* __restrict__ out, int n) {
    int lane = threadIdx.x & 31;
    int w = (blockIdx.x * blockDim.x + threadIdx.x) >> 5;
    int nw = (gridDim.x * blockDim.x) >> 5;
    for (int d = w; d < n; d += nw) {
        int r0 = rs[d], r1 = rs[d + 1];
        float acc = 0.f;
        for (int j = r0 + lane; j < r1; j += 32) {
            int s = csr[j];
            acc += dinv[s] * h[s];
        }
        #pragma unroll
        for (int o = 16; o > 0; o >>= 1) acc += __shfl_xor_sync(FULLM, acc, o);
        if (lane == 0) {
            float dd = dinv[d];
            float v = dd * acc + dd * dd * h[d];
            out[d] = 1.f / (1.f + expf(-v));
        }
    }
}

// ------------------------------- host side ---------------------------------
static inline int nblk(long long n) { return (int)((n + TPB - 1) / TPB); }
static inline int gridA(int n) { int g = (n + 7) / 8; return g > 2048 ? 2048 : g; }

struct DevPtrs {
    float *X0, *X1, *X2, *H, *Y, *YD3, *YU0, *YU1;
    int *deg, *cursor, *rs0, *rs1, *rs2, *rs3;
    float *dinv0_2, *dinv0_1, *dinv1, *dinv2, *dinv3;
    int *csr0, *csr1, *csr2, *csr3;
    int *src1, *dst1, *src2, *dst2, *src3, *dst3, *cnt;
    float *keys, *keysOut, *stats, *h1;
    int *idx, *perm0, *perm1, *perm2, *map0, *map1, *map2;
    void* cubtmp;
};

#define GETP(sym, field, type) { void* q; cudaGetSymbolAddress(&q, sym); p.field = (type)q; }

static void get_ptrs(DevPtrs& p) {
    GETP(g_X0, X0, float*) GETP(g_X1, X1, float*) GETP(g_X2, X2, float*)
    GETP(g_H, H, float*) GETP(g_Y, Y, float*)
    GETP(g_YD3, YD3, float*) GETP(g_YU0, YU0, float*) GETP(g_YU1, YU1, float*)
    GETP(g_deg, deg, int*) GETP(g_cursor, cursor, int*)
    GETP(g_rs0, rs0, int*) GETP(g_rs1, rs1, int*) GETP(g_rs2, rs2, int*) GETP(g_rs3, rs3, int*)
    GETP(g_dinv0_2, dinv0_2, float*) GETP(g_dinv0_1, dinv0_1, float*)
    GETP(g_dinv1, dinv1, float*) GETP(g_dinv2, dinv2, float*) GETP(g_dinv3, dinv3, float*)
    GETP(g_csr0, csr0, int*) GETP(g_csr1, csr1, int*) GETP(g_csr2, csr2, int*) GETP(g_csr3, csr3, int*)
    GETP(g_src1, src1, int*) GETP(g_dst1, dst1, int*)
    GETP(g_src2, src2, int*) GETP(g_dst2, dst2, int*)
    GETP(g_src3, src3, int*) GETP(g_dst3, dst3, int*)
    GETP(g_cnt, cnt, int*)
    GETP(g_keys, keys, float*) GETP(g_keysOut, keysOut, float*)
    GETP(g_statsAll, stats, float*) GETP(g_h1, h1, float*)
    GETP(g_idx, idx, int*)
    GETP(g_perm0, perm0, int*) GETP(g_perm1, perm1, int*) GETP(g_perm2, perm2, int*)
    GETP(g_map0, map0, int*) GETP(g_map1, map1, int*) GETP(g_map2, map2, int*)
    GETP(g_cubtmp, cubtmp, void*)
}

static cudaStream_t s_side;
static cudaEvent_t  s_evF[5], s_evJ[5];
static bool s_init = false;

static void fork_side(int i) {
    cudaEventRecord(s_evF[i], 0);
    cudaStreamWaitEvent(s_side, s_evF[i], 0);
}
static void join_side(int i) {
    cudaEventRecord(s_evJ[i], s_side);
    cudaStreamWaitEvent(0, s_evJ[i], 0);
}

// side-stream CSR build: cub scan + prep + scatter
static void csr_chain(const DevPtrs& p, const int* srcC, const int* dstC,
                      const int* cntp, int nfix, int n, int* rs, int* csr,
                      float* dinvA, float fillA, float* dinvB, float fillB) {
    size_t tb = 0;
    cub::DeviceScan::ExclusiveSum(nullptr, tb, p.deg, rs, n + 1, s_side);
    cub::DeviceScan::ExclusiveSum(p.cubtmp, tb, p.deg, rs, n + 1, s_side);
    k_prep<<<nblk(n), TPB, 0, s_side>>>(rs, p.cursor, dinvA, fillA, dinvB, fillB, n);
    k_scatter<<<GRIDE, TPB, 0, s_side>>>(srcC, dstC, p.cursor, csr, cntp, nfix);
}

static void radix_sort(const DevPtrs& p, int* permOut, int n) {
    size_t tb = 0;
    cub::DeviceRadixSort::SortPairsDescending(nullptr, tb, p.keys, p.keysOut,
                                              p.idx, permOut, n, 0, 32, (cudaStream_t)0);
    cub::DeviceRadixSort::SortPairsDescending(p.cubtmp, tb, p.keys, p.keysOut,
                                              p.idx, permOut, n, 0, 32, (cudaStream_t)0);
}

extern "C" void kernel_launch(void* const* d_in, const int* in_sizes, int n_in,
                              void* d_out, int out_size) {
    if (!s_init) {   // first call is the uncaptured correctness run
        cudaStreamCreateWithFlags(&s_side, cudaStreamNonBlocking);
        for (int i = 0; i < 5; i++) {
            cudaEventCreateWithFlags(&s_evF[i], cudaEventDisableTiming);
            cudaEventCreateWithFlags(&s_evJ[i], cudaEventDisableTiming);
        }
        s_init = true;
    }

    const float* x_in = (const float*)d_in[0];
    const int* ei     = (const int*)d_in[1];
    const int* src0 = ei;
    const int* dst0 = ei + cNE;
    const float* Wd[4] = {(const float*)d_in[2],  (const float*)d_in[5],
                          (const float*)d_in[8],  (const float*)d_in[11]};
    const float* gd[4] = {(const float*)d_in[3],  (const float*)d_in[6],
                          (const float*)d_in[9],  (const float*)d_in[12]};
    const float* bd[4] = {(const float*)d_in[4],  (const float*)d_in[7],
                          (const float*)d_in[10], (const float*)d_in[13]};
    const float* pw[3] = {(const float*)d_in[14], (const float*)d_in[15],
                          (const float*)d_in[16]};
    const float* Wu[2] = {(const float*)d_in[17], (const float*)d_in[20]};
    const float* gu[2] = {(const float*)d_in[18], (const float*)d_in[21]};
    const float* bu[2] = {(const float*)d_in[19], (const float*)d_in[22]};
    const float* Wout  = (const float*)d_in[23];

    DevPtrs p;
    get_ptrs(p);
    float* S[6];
    for (int i = 0; i < 6; i++) S[i] = p.stats + i * 128;

    // ===== phase 0: block0 matmul || level-0 CSR build =====
    fork_side(0);
    k_zeroi<<<nblk(cN0 + 1), TPB, 0, s_side>>>(p.deg, cN0 + 1);
    k_hist0<<<GRIDE, TPB, 0, s_side>>>(dst0, p.deg);
    csr_chain(p, src0, dst0, nullptr, cNE, cN0, p.rs0, p.csr0,
              p.dinv0_2, 2.0f, p.dinv0_1, 1.0f);
    k_mm0<<<nblk((long long)cN0 * 16), TPB>>>(x_in, Wd[0], p.H, S[0], cN0);
    join_side(0);
    k_agg_bn<<<gridA(cN0), TPB>>>(p.rs0, p.csr0, p.dinv0_2, p.H, p.Y, S[0], 2.0f, cN0);
    k_bn_score<<<2048, TPB>>>(p.Y, gd[0], bd[0], S[0], p.X0, pw[0],
                              p.keys, p.idx, p.map0, p.deg, cN0);

    // ===== pool 0 + block 1 =====
    radix_sort(p, p.perm0, cN0);
    fork_side(1);
    k_mapset<<<nblk(cN1), TPB, 0, s_side>>>(p.map0, p.perm0, cN1, &p.cnt[0]);
    k_remap_hist<<<GRIDE, TPB, 0, s_side>>>(src0, dst0, p.map0, p.src1, p.dst1,
                                            &p.cnt[0], p.deg, nullptr, cNE);
    csr_chain(p, p.src1, p.dst1, &p.cnt[0], 0, cN1, p.rs1, p.csr1,
              p.dinv1, 2.0f, nullptr, 0.f);
    k_mm_pool<<<nblk((long long)cN1 * 4), TPB>>>(p.X0, Wd[1], p.perm0, p.keysOut,
                                                 p.H, S[1], cN1);
    join_side(1);
    k_agg_bn<<<gridA(cN1), TPB>>>(p.rs1, p.csr1, p.dinv1, p.H, p.Y, S[1], 2.0f, cN1);
    k_bn_score<<<1024, TPB>>>(p.Y, gd[1], bd[1], S[1], p.X1, pw[1],
                              p.keys, p.idx, p.map1, p.deg, cN1);

    // ===== pool 1 + block 2 =====
    radix_sort(p, p.perm1, cN1);
    fork_side(2);
    k_mapset<<<nblk(cN2), TPB, 0, s_side>>>(p.map1, p.perm1, cN2, &p.cnt[1]);
    k_remap_hist<<<GRIDE, TPB, 0, s_side>>>(p.src1, p.dst1, p.map1, p.src2, p.dst2,
                                            &p.cnt[1], p.deg, &p.cnt[0], 0);
    csr_chain(p, p.src2, p.dst2, &p.cnt[1], 0, cN2, p.rs2, p.csr2,
              p.dinv2, 2.0f, nullptr, 0.f);
    k_mm_pool<<<nblk((long long)cN2 * 4), TPB>>>(p.X1, Wd[2], p.perm1, p.keysOut,
                                                 p.H, S[2], cN2);
    join_side(2);
    k_agg_bn<<<gridA(cN2), TPB>>>(p.rs2, p.csr2, p.dinv2, p.H, p.Y, S[2], 2.0f, cN2);
    k_bn_score<<<512, TPB>>>(p.Y, gd[2], bd[2], S[2], p.X2, pw[2],
                             p.keys, p.idx, p.map2, p.deg, cN2);

    // ===== pool 2 + block 3 =====
    radix_sort(p, p.perm2, cN2);
    fork_side(3);
    k_mapset<<<nblk(cN3), TPB, 0, s_side>>>(p.map2, p.perm2, cN3, &p.cnt[2]);
    k_remap_hist<<<GRIDE, TPB, 0, s_side>>>(p.src2, p.dst2, p.map2, p.src3, p.dst3,
                                            &p.cnt[2], p.deg, &p.cnt[1], 0);
    csr_chain(p, p.src3, p.dst3, &p.cnt[2], 0, cN3, p.rs3, p.csr3,
              p.dinv3, 2.0f, nullptr, 0.f);
    k_mm_pool<<<nblk((long long)cN3 * 4), TPB>>>(p.X2, Wd[3], p.perm2, p.keysOut,
                                                 p.H, S[3], cN3);
    join_side(3);
    k_agg_bn<<<gridA(cN3), TPB>>>(p.rs3, p.csr3, p.dinv3, p.H, p.YD3, S[3], 2.0f, cN3);

    // ===== up path (BN of previous block fused into each consumer) =====
    // up0: rows = X2 + relu(bn(YD3[map2])), conv over level-2 CSR
    k_mm_res_bn<<<nblk((long long)cN2 * 4), TPB>>>(p.X2, p.YD3, p.map2,
                                                   gd[3], bd[3], S[3], 1.f / cN3,
                                                   Wu[0], p.H, S[4], cN2);
    k_agg_bn<<<gridA(cN2), TPB>>>(p.rs2, p.csr2, p.dinv2, p.H, p.YU0, S[4], 2.0f, cN2);

    // up1: rows = X1 + relu(bn(YU0[map1])), conv over level-1 CSR
    k_mm_res_bn<<<nblk((long long)cN1 * 4), TPB>>>(p.X1, p.YU0, p.map1,
                                                   gu[0], bu[0], S[4], 1.f / cN2,
                                                   Wu[1], p.H, S[5], cN1);
    k_agg_bn<<<gridA(cN1), TPB>>>(p.rs1, p.csr1, p.dinv1, p.H, p.YU1, S[5], 2.0f, cN1);

    // final: rows = X0 + relu(bn(YU1[map0])), 1-ch conv (fill=1) + sigmoid
    k_mm1_res_bn<<<nblk(cN0), TPB>>>(p.X0, p.YU1, p.map0,
                                     gu[1], bu[1], S[5], 1.f / cN1,
                                     Wout, p.h1, cN0);
    k_csr_final<<<2048, TPB>>>(p.rs0, p.csr0, p.dinv0_1, p.h1, (float*)d_out, cN0);
}